// round 7
// baseline (speedup 1.0000x reference)
#include <cuda_runtime.h>
#include <cuda_bf16.h>

#define KE_CONST 138.96f

// Packed per-atom {charge, sys_idx-as-float-bits}. 1<<19 * 8B = 4 MB static
// scratch (allocation-free per harness rules). N in this problem is 262144.
#define QS_CAP (1 << 19)
__device__ float2 g_qs[QS_CAP];

// Pack {q, sys} AND zero the output in one launch (saves a ~3us tiny-kernel slot).
__global__ void pack_qs_kernel(const float* __restrict__ q,
                               const int*   __restrict__ sys,
                               float* __restrict__ out,
                               int N, int S) {
    int t = blockIdx.x * blockDim.x + threadIdx.x;
    if (t < N) g_qs[t] = make_float2(q[t], __int_as_float(sys[t]));
    if (t < S) out[t] = 0.0f;
}

__device__ __forceinline__ float chi_fn(float d) {
    float u  = 2.0f * d;
    float u3 = u * u * u;
    // phi = 1 + u^3 * (-10 + u*(15 - 6u)), clamped to 0 for u >= 1
    float p   = fmaf(u, fmaf(u, -6.0f, 15.0f), -10.0f);
    float phi = (u < 1.0f) ? fmaf(u3, p, 1.0f) : 0.0f;
    float inv_d  = __fdividef(1.0f, d);
    float inv_rs = rsqrtf(fmaf(d, d, 1.0f));
    return fmaf(phi, inv_rs, (1.0f - phi) * inv_d);
}

// Stage one 4-pair vector: masks + predicated gathers (batched for MLP).
struct Staged4 {
    float qi[4], qj[4], d[4];
    int   s[4];
    bool  m[4];
};

__device__ __forceinline__ void stage4(const int4 ii, const int4 jj, const float4 dd,
                                       const float* __restrict__ q, Staged4& st)
{
    const int iv[4] = {ii.x, ii.y, ii.z, ii.w};
    const int jv[4] = {jj.x, jj.y, jj.z, jj.w};
    st.d[0] = dd.x; st.d[1] = dd.y; st.d[2] = dd.z; st.d[3] = dd.w;
#pragma unroll
    for (int k = 0; k < 4; k++) {
        st.m[k] = iv[k] < jv[k];
        float2 qs = st.m[k] ? __ldg(&g_qs[iv[k]]) : make_float2(0.0f, 0.0f);
        st.qi[k] = qs.x;
        st.s[k]  = __float_as_int(qs.y);
        st.qj[k] = st.m[k] ? __ldg(q + jv[k]) : 0.0f;
    }
}

__device__ __forceinline__ void commit4(const Staged4& st, float* __restrict__ sbin)
{
#pragma unroll
    for (int k = 0; k < 4; k++) {
        float e = st.qi[k] * st.qj[k] * chi_fn(st.d[k]);
        if (st.m[k]) atomicAdd(&sbin[st.s[k]], e);
    }
}

__global__ void __launch_bounds__(256, 6)
coulomb_kernel(const int*   __restrict__ pair,
               const float* __restrict__ dij,
               const float* __restrict__ q,
               float*       __restrict__ out,
               int P, int S)
{
    extern __shared__ float sbin[];
    for (int s = threadIdx.x; s < S; s += blockDim.x) sbin[s] = 0.0f;
    __syncthreads();

    const int4*   pi4 = reinterpret_cast<const int4*>(pair);        // idx_i row
    const int4*   pj4 = reinterpret_cast<const int4*>(pair + P);    // idx_j row
    const float4* d4  = reinterpret_cast<const float4*>(dij);

    const int nvec   = P >> 2;
    const int stride = gridDim.x * blockDim.x;
    const int gtid   = blockIdx.x * blockDim.x + threadIdx.x;

    // Unroll x2: stage 8 pairs (16 gathers in flight) before the dependent
    // shared-atomic drain — deepens MLP on the L1tex queue while the crossbar
    // retires the previous batch's ATOMS.
    int v = gtid;
    for (; v + stride < nvec; v += 2 * stride) {
        int4   iiA = __ldcs(pi4 + v);
        int4   jjA = __ldcs(pj4 + v);
        float4 ddA = __ldcs(d4  + v);
        int4   iiB = __ldcs(pi4 + v + stride);
        int4   jjB = __ldcs(pj4 + v + stride);
        float4 ddB = __ldcs(d4  + v + stride);

        Staged4 sA, sB;
        stage4(iiA, jjA, ddA, q, sA);
        stage4(iiB, jjB, ddB, q, sB);
        commit4(sA, sbin);
        commit4(sB, sbin);
    }
    // Leftover single vector (when nvec/stride is odd for this thread)
    for (; v < nvec; v += stride) {
        int4   ii = __ldcs(pi4 + v);
        int4   jj = __ldcs(pj4 + v);
        float4 dd = __ldcs(d4  + v);
        Staged4 st;
        stage4(ii, jj, dd, q, st);
        commit4(st, sbin);
    }

    // Scalar tail (P % 4 != 0 insurance)
    for (int p = (nvec << 2) + gtid; p < P; p += stride) {
        int   i = __ldg(pair + p);
        int   j = __ldg(pair + P + p);
        float d = __ldg(dij + p);
        bool  m = i < j;
        float2 qs = m ? __ldg(&g_qs[i]) : make_float2(0.0f, 0.0f);
        float qj  = m ? __ldg(q + j) : 0.0f;
        float e   = qs.x * qj * chi_fn(d);
        if (m) atomicAdd(&sbin[__float_as_int(qs.y)], e);
    }

    __syncthreads();

    // Flush per-CTA bins to global (apply KE scale once here).
    for (int s = threadIdx.x; s < S; s += blockDim.x) {
        float vbin = sbin[s];
        if (vbin != 0.0f) atomicAdd(&out[s], vbin * KE_CONST);
    }
}

// Fallback (N > QS_CAP): unpacked gathers, same structure.
__global__ void __launch_bounds__(256, 6)
coulomb_kernel_unpacked(const int*   __restrict__ pair,
                        const float* __restrict__ dij,
                        const float* __restrict__ q,
                        const int*   __restrict__ sys,
                        float*       __restrict__ out,
                        int P, int S)
{
    extern __shared__ float sbin[];
    for (int s = threadIdx.x; s < S; s += blockDim.x) sbin[s] = 0.0f;
    __syncthreads();

    const int stride = gridDim.x * blockDim.x;
    const int gtid   = blockIdx.x * blockDim.x + threadIdx.x;
    for (int p = gtid; p < P; p += stride) {
        int   i = __ldg(pair + p);
        int   j = __ldg(pair + P + p);
        float d = __ldg(dij + p);
        bool  m = i < j;
        float qi = m ? __ldg(q + i)  : 0.0f;
        float qj = m ? __ldg(q + j)  : 0.0f;
        int   s  = m ? __ldg(sys + i) : 0;
        float e  = qi * qj * chi_fn(d);
        if (m) atomicAdd(&sbin[s], e);
    }
    __syncthreads();
    for (int s = threadIdx.x; s < S; s += blockDim.x) {
        float vbin = sbin[s];
        if (vbin != 0.0f) atomicAdd(&out[s], vbin * KE_CONST);
    }
}

__global__ void zero_out_kernel(float* __restrict__ out, int S) {
    int t = blockIdx.x * blockDim.x + threadIdx.x;
    if (t < S) out[t] = 0.0f;
}

extern "C" void kernel_launch(void* const* d_in, const int* in_sizes, int n_in,
                              void* d_out, int out_size)
{
    const int*   pair = (const int*)  d_in[0];  // (2, P) int32
    const float* dij  = (const float*)d_in[1];  // (P, 1) float32
    const float* q    = (const float*)d_in[2];  // (N, 1) float32
    const int*   sys  = (const int*)  d_in[3];  // (N,)   int32
    float*       out  = (float*)d_out;

    const int P = in_sizes[1];      // number of pairs
    const int N = in_sizes[2];      // number of atoms
    const int S = out_size;         // num_systems

    const int threads = 256;
    const int blocks  = 1184;       // 148 SMs * up to 8 CTAs
    const size_t smem = (size_t)S * sizeof(float);

    if (N <= QS_CAP) {
        // pack also zeroes out (S <= N assumed; guarded anyway below)
        int pn = (N > S ? N : S);
        pack_qs_kernel<<<(pn + 255) / 256, 256>>>(q, sys, out, N, S);
        coulomb_kernel<<<blocks, threads, smem>>>(pair, dij, q, out, P, S);
    } else {
        zero_out_kernel<<<(S + 255) / 256, 256>>>(out, S);
        coulomb_kernel_unpacked<<<blocks, threads, smem>>>(pair, dij, q, sys, out, P, S);
    }
}

// round 8
// speedup vs baseline: 1.4287x; 1.4287x over previous
#include <cuda_runtime.h>
#include <cuda_bf16.h>

#define KE_CONST 138.96f

// Packed per-atom {charge, sys_idx-as-float-bits}. 1<<19 * 8B = 4 MB static
// scratch (allocation-free per harness rules). N in this problem is 262144.
#define QS_CAP (1 << 19)
__device__ float2 g_qs[QS_CAP];

// Pack {q, sys} AND zero the output in one launch (saves the ~3.4us
// standalone zero kernel that serialized ahead of the main kernel).
__global__ void pack_qs_kernel(const float* __restrict__ q,
                               const int*   __restrict__ sys,
                               float* __restrict__ out,
                               int N, int S) {
    int t = blockIdx.x * blockDim.x + threadIdx.x;
    if (t < N) g_qs[t] = make_float2(q[t], __int_as_float(sys[t]));
    if (t < S) out[t] = 0.0f;
}

__global__ void zero_out_kernel(float* __restrict__ out, int S) {
    int t = blockIdx.x * blockDim.x + threadIdx.x;
    if (t < S) out[t] = 0.0f;
}

__device__ __forceinline__ float chi_fn(float d) {
    float u  = 2.0f * d;
    float u2 = u * u;
    float u3 = u2 * u;
    // phi = 1 + u^3 * (-10 + u*(15 - 6u)), clamped to 0 for u >= 1
    float p   = fmaf(u, fmaf(u, -6.0f, 15.0f), -10.0f);
    float phi = (u < 1.0f) ? fmaf(u3, p, 1.0f) : 0.0f;
    float inv_d  = __fdividef(1.0f, d);
    float inv_rs = rsqrtf(fmaf(d, d, 1.0f));
    return fmaf(phi, inv_rs, (1.0f - phi) * inv_d);
}

template <bool PACKED>
__device__ __forceinline__ void process_pair(
    int i, int j, float d,
    const float* __restrict__ q,
    const int*   __restrict__ sys,
    float* __restrict__ sbin)
{
    const bool m = (i < j);
    // Branchless predicated gathers: compiler emits @P LDG, keeping loads
    // batched for MLP instead of a divergent BSSY/BSYNC region.
    float qi, qj;
    int   s;
    if (PACKED) {
        float2 qs = m ? __ldg(&g_qs[i]) : make_float2(0.0f, 0.0f);  // one LDG.64
        qi = qs.x;
        s  = __float_as_int(qs.y);
    } else {
        qi = m ? __ldg(q + i)  : 0.0f;
        s  = m ? __ldg(sys + i) : 0;
    }
    qj = m ? __ldg(q + j) : 0.0f;

    float e = qi * qj * chi_fn(d);
    if (m) atomicAdd(&sbin[s], e);
}

template <bool PACKED>
__global__ void __launch_bounds__(256)
coulomb_kernel(const int*   __restrict__ pair,
               const float* __restrict__ dij,
               const float* __restrict__ q,
               const int*   __restrict__ sys,
               float*       __restrict__ out,
               int P, int S)
{
    extern __shared__ float sbin[];
    for (int s = threadIdx.x; s < S; s += blockDim.x) sbin[s] = 0.0f;
    __syncthreads();

    const int4*   pi4 = reinterpret_cast<const int4*>(pair);        // idx_i row
    const int4*   pj4 = reinterpret_cast<const int4*>(pair + P);    // idx_j row
    const float4* d4  = reinterpret_cast<const float4*>(dij);

    const int nvec   = P >> 2;
    const int stride = gridDim.x * blockDim.x;
    const int gtid   = blockIdx.x * blockDim.x + threadIdx.x;

    for (int v = gtid; v < nvec; v += stride) {
        // Streaming data is touched once: evict-first so it doesn't thrash
        // L2 against the hot gather working set.
        int4   ii = __ldcs(pi4 + v);
        int4   jj = __ldcs(pj4 + v);
        float4 dd = __ldcs(d4  + v);
        process_pair<PACKED>(ii.x, jj.x, dd.x, q, sys, sbin);
        process_pair<PACKED>(ii.y, jj.y, dd.y, q, sys, sbin);
        process_pair<PACKED>(ii.z, jj.z, dd.z, q, sys, sbin);
        process_pair<PACKED>(ii.w, jj.w, dd.w, q, sys, sbin);
    }

    // Scalar tail (P % 4 != 0 insurance)
    for (int p = (nvec << 2) + gtid; p < P; p += stride) {
        int   i = __ldg(pair + p);
        int   j = __ldg(pair + P + p);
        float d = __ldg(dij + p);
        process_pair<PACKED>(i, j, d, q, sys, sbin);
    }

    __syncthreads();

    // Flush per-CTA bins to global (apply KE scale once here).
    for (int s = threadIdx.x; s < S; s += blockDim.x) {
        float v = sbin[s];
        if (v != 0.0f) atomicAdd(&out[s], v * KE_CONST);
    }
}

extern "C" void kernel_launch(void* const* d_in, const int* in_sizes, int n_in,
                              void* d_out, int out_size)
{
    const int*   pair = (const int*)  d_in[0];  // (2, P) int32
    const float* dij  = (const float*)d_in[1];  // (P, 1) float32
    const float* q    = (const float*)d_in[2];  // (N, 1) float32
    const int*   sys  = (const int*)  d_in[3];  // (N,)   int32
    float*       out  = (float*)d_out;

    const int P = in_sizes[1];      // number of pairs
    const int N = in_sizes[2];      // number of atoms
    const int S = out_size;         // num_systems

    const int threads = 256;
    const int blocks  = 1184;       // 8 CTAs/SM * 148 SMs, exactly one wave
    const size_t smem = (size_t)S * sizeof(float);

    if (N <= QS_CAP) {
        int pn = (N > S ? N : S);
        pack_qs_kernel<<<(pn + 255) / 256, 256>>>(q, sys, out, N, S);
        coulomb_kernel<true><<<blocks, threads, smem>>>(pair, dij, q, sys, out, P, S);
    } else {
        zero_out_kernel<<<(S + 255) / 256, 256>>>(out, S);
        coulomb_kernel<false><<<blocks, threads, smem>>>(pair, dij, q, sys, out, P, S);
    }
}

// round 9
// speedup vs baseline: 1.4544x; 1.0180x over previous
#include <cuda_runtime.h>
#include <cuda_bf16.h>

#define KE_CONST 138.96f

// Packed per-atom {charge, sys_idx-as-float-bits}. 1<<19 * 8B = 4 MB static
// scratch (allocation-free per harness rules). N in this problem is 262144.
#define QS_CAP (1 << 19)
__device__ float2 g_qs[QS_CAP];

// Vectorized pack: 4 atoms/thread (float4 q + int4 sys -> 2x float4 stores),
// and zero the output array in the same launch. This kernel serializes ahead
// of the main kernel in the graph, so its latency is on the critical path.
__global__ void pack_qs_kernel(const float* __restrict__ q,
                               const int*   __restrict__ sys,
                               float* __restrict__ out,
                               int N, int S) {
    int t = blockIdx.x * blockDim.x + threadIdx.x;
    int nvec = N >> 2;
    if (t < nvec) {
        float4 qq = __ldg(reinterpret_cast<const float4*>(q) + t);
        int4   ss = __ldg(reinterpret_cast<const int4*>(sys) + t);
        float4 lo = make_float4(qq.x, __int_as_float(ss.x), qq.y, __int_as_float(ss.y));
        float4 hi = make_float4(qq.z, __int_as_float(ss.z), qq.w, __int_as_float(ss.w));
        float4* dst = reinterpret_cast<float4*>(&g_qs[t << 2]);
        dst[0] = lo;
        dst[1] = hi;
    }
    // Scalar tail for N % 4 != 0
    int tail = (nvec << 2) + t;
    if (t < (N & 3)) {
        // only first few threads handle the tail elements
        g_qs[tail] = make_float2(q[tail], __int_as_float(sys[tail]));
    }
    if (t < S) out[t] = 0.0f;
}

__global__ void zero_out_kernel(float* __restrict__ out, int S) {
    int t = blockIdx.x * blockDim.x + threadIdx.x;
    if (t < S) out[t] = 0.0f;
}

__device__ __forceinline__ float chi_fn(float d) {
    float u  = 2.0f * d;
    float u2 = u * u;
    float u3 = u2 * u;
    // phi = 1 + u^3 * (-10 + u*(15 - 6u)), clamped to 0 for u >= 1
    float p   = fmaf(u, fmaf(u, -6.0f, 15.0f), -10.0f);
    float phi = (u < 1.0f) ? fmaf(u3, p, 1.0f) : 0.0f;
    float inv_d  = __fdividef(1.0f, d);
    float inv_rs = rsqrtf(fmaf(d, d, 1.0f));
    return fmaf(phi, inv_rs, (1.0f - phi) * inv_d);
}

template <bool PACKED>
__device__ __forceinline__ void process_pair(
    int i, int j, float d,
    const float* __restrict__ q,
    const int*   __restrict__ sys,
    float* __restrict__ sbin)
{
    const bool m = (i < j);
    // Branchless predicated gathers: compiler emits @P LDG, keeping loads
    // batched for MLP instead of a divergent BSSY/BSYNC region.
    float qi, qj;
    int   s;
    if (PACKED) {
        float2 qs = m ? __ldg(&g_qs[i]) : make_float2(0.0f, 0.0f);  // one LDG.64
        qi = qs.x;
        s  = __float_as_int(qs.y);
    } else {
        qi = m ? __ldg(q + i)  : 0.0f;
        s  = m ? __ldg(sys + i) : 0;
    }
    qj = m ? __ldg(q + j) : 0.0f;

    float e = qi * qj * chi_fn(d);
    if (m) atomicAdd(&sbin[s], e);
}

template <bool PACKED>
__global__ void __launch_bounds__(256, 8)
coulomb_kernel(const int*   __restrict__ pair,
               const float* __restrict__ dij,
               const float* __restrict__ q,
               const int*   __restrict__ sys,
               float*       __restrict__ out,
               int P, int S)
{
    extern __shared__ float sbin[];
    for (int s = threadIdx.x; s < S; s += blockDim.x) sbin[s] = 0.0f;
    __syncthreads();

    const int4*   pi4 = reinterpret_cast<const int4*>(pair);        // idx_i row
    const int4*   pj4 = reinterpret_cast<const int4*>(pair + P);    // idx_j row
    const float4* d4  = reinterpret_cast<const float4*>(dij);

    const int nvec   = P >> 2;
    const int stride = gridDim.x * blockDim.x;
    const int gtid   = blockIdx.x * blockDim.x + threadIdx.x;

    for (int v = gtid; v < nvec; v += stride) {
        // Streaming data is touched once: evict-first so it doesn't thrash
        // L2 against the hot gather working set.
        int4   ii = __ldcs(pi4 + v);
        int4   jj = __ldcs(pj4 + v);
        float4 dd = __ldcs(d4  + v);
        process_pair<PACKED>(ii.x, jj.x, dd.x, q, sys, sbin);
        process_pair<PACKED>(ii.y, jj.y, dd.y, q, sys, sbin);
        process_pair<PACKED>(ii.z, jj.z, dd.z, q, sys, sbin);
        process_pair<PACKED>(ii.w, jj.w, dd.w, q, sys, sbin);
    }

    // Scalar tail (P % 4 != 0 insurance)
    for (int p = (nvec << 2) + gtid; p < P; p += stride) {
        int   i = __ldg(pair + p);
        int   j = __ldg(pair + P + p);
        float d = __ldg(dij + p);
        process_pair<PACKED>(i, j, d, q, sys, sbin);
    }

    __syncthreads();

    // Flush per-CTA bins to global (apply KE scale once here). No zero-guard:
    // ~99.9% of bins are nonzero per CTA, the branch is pure overhead.
    for (int s = threadIdx.x; s < S; s += blockDim.x) {
        atomicAdd(&out[s], sbin[s] * KE_CONST);
    }
}

extern "C" void kernel_launch(void* const* d_in, const int* in_sizes, int n_in,
                              void* d_out, int out_size)
{
    const int*   pair = (const int*)  d_in[0];  // (2, P) int32
    const float* dij  = (const float*)d_in[1];  // (P, 1) float32
    const float* q    = (const float*)d_in[2];  // (N, 1) float32
    const int*   sys  = (const int*)  d_in[3];  // (N,)   int32
    float*       out  = (float*)d_out;

    const int P = in_sizes[1];      // number of pairs
    const int N = in_sizes[2];      // number of atoms
    const int S = out_size;         // num_systems

    const int threads = 256;
    const int blocks  = 1184;       // 8 CTAs/SM * 148 SMs, exactly one wave
    const size_t smem = (size_t)S * sizeof(float);

    if (N <= QS_CAP) {
        int nvec = N >> 2;
        int work = (nvec > S ? nvec : S);
        pack_qs_kernel<<<(work + 255) / 256, 256>>>(q, sys, out, N, S);
        coulomb_kernel<true><<<blocks, threads, smem>>>(pair, dij, q, sys, out, P, S);
    } else {
        zero_out_kernel<<<(S + 255) / 256, 256>>>(out, S);
        coulomb_kernel<false><<<blocks, threads, smem>>>(pair, dij, q, sys, out, P, S);
    }
}